// round 2
// baseline (speedup 1.0000x reference)
#include <cuda_runtime.h>
#include <math.h>

#define NUM_INITS 64
#define PSTRIDE   46922
#define NBATCH    128
#define TILE      16
#define NPAIR     8          // image pairs per block
#define NTILES    8
#define THREADS   384

#define OFF_WDENSE 832       // float offset of dense weights in a param row
#define OFF_BDENSE 46912

// ---- shared memory layout (float offsets) ----
#define SM_IMG   0                 // 8 pairs * 784 float2 = 12544 floats (50176B)
#define SM_WCP   12544             // 800 float2 (w,w duplicated)  = 1600 floats
#define SM_BIAS  14144             // 32 floats
#define SM_POOL  14176             // 8 pairs * 292 float2 = 4672 floats
#define SM_WDP   18848             // 10 outs * 292 float2 (dup)   = 5840 floats
#define SM_RED   24688             // 320 float2 = 640 floats
#define SM_LOG   25328             // 160 floats
#define SM_FLOATS 25488
#define SMEM_BYTES (SM_FLOATS * 4) // 101952 B -> 2 blocks/SM

#define POOL_STR 292               // float2 stride per image pair (2ch*144 + pad)
#define WD_STR   292               // float2 stride per output row (288 + pad)

typedef unsigned long long ull;

__device__ __forceinline__ float2 u2f(ull v) {
    float2 f; asm("mov.b64 {%0, %1}, %2;" : "=f"(f.x), "=f"(f.y) : "l"(v)); return f;
}
// packed fp32x2 fma: acc = a*b + acc  (bit-exact fp32 per lane)
#define FMA2(acc, a, b) asm("fma.rn.f32x2 %0, %1, %2, %0;" : "+l"(acc) : "l"(a), "l"(b))

__global__ void __launch_bounds__(THREADS, 2)
fused_paramevaler_kernel(const float* __restrict__ params,
                         const float* __restrict__ batch,
                         float* __restrict__ out)
{
    extern __shared__ float sm[];
    float2*       s_imgf2  = (float2*)(sm + SM_IMG);
    float2*       s_wcpf2  = (float2*)(sm + SM_WCP);
    float*        s_bias   = sm + SM_BIAS;
    float2*       s_poolf2 = (float2*)(sm + SM_POOL);
    float2*       s_wdpf2  = (float2*)(sm + SM_WDP);
    float2*       s_redf2  = (float2*)(sm + SM_RED);
    float*        s_log    = sm + SM_LOG;

    const int blk  = blockIdx.x;           // 0..511
    const int init = blk >> 3;
    const int n0   = (blk & (NTILES - 1)) * TILE;
    const int t    = threadIdx.x;

    const float* __restrict__ P = params + (size_t)init * PSTRIDE;

    // ---- Stage images as f32x2 image-pairs (coalesced float4 reads) ----
    for (int u = t; u < NPAIR * 196; u += THREADS) {
        int pr = u / 196, q = u % 196;
        float4 a = ((const float4*)(batch + (size_t)(n0 + 2*pr    ) * 784))[q];
        float4 b = ((const float4*)(batch + (size_t)(n0 + 2*pr + 1) * 784))[q];
        float4* dst = (float4*)s_imgf2;          // 2 float2 per float4 slot
        dst[pr * 392 + q * 2    ] = make_float4(a.x, b.x, a.y, b.y);
        dst[pr * 392 + q * 2 + 1] = make_float4(a.z, b.z, a.w, b.w);
    }
    // ---- Stage conv weights duplicated (w,w) + bias ----
    for (int u = t; u < 800; u += THREADS) {
        float w = P[u];
        s_wcpf2[u] = make_float2(w, w);
    }
    if (t < 32) s_bias[t] = P[800 + t];
    __syncthreads();

    // Conv role: (pair, pooled-row, quarter) -> exactly 384 threads
    const int pair  = t / 48;            // 0..7
    const int rem   = t % 48;
    const int prow  = rem >> 2;          // 0..11
    const int quart = rem & 3;           // 0..3
    const int x0    = quart * 6;         // conv-col base
    const float2* __restrict__ ipbase = s_imgf2 + pair * 784 + prow * 2 * 28 + x0;

    // Dense role: t<160 -> (pair, output-pair, k-quarter)
    const int dpair = t / 20;
    const int drem  = t % 20;
    const int dop   = drem >> 2;         // 0..4 (outputs 2*dop, 2*dop+1)
    const int dks   = drem & 3;          // 0..3 (k chunk of 72 over 288)
    ull dacc0a = 0, dacc0b = 0, dacc1a = 0, dacc1b = 0;

    for (int ci = 0; ci < 16; ++ci) {
        const int c0 = 2 * ci;

        // ---- Stage dense weights for channels (c0, c0+1), duplicated (w,w) ----
        for (int u = t; u < 1440; u += THREADS) {
            int o = u / 144, j = u % 144;
            float2 w = *(const float2*)(P + OFF_WDENSE + (size_t)o * 4608 + c0 * 144 + 2 * j);
            *(float4*)(&s_wdpf2[o * WD_STR + 2 * j]) = make_float4(w.x, w.x, w.y, w.y);
        }

        // ---- Conv: 2 channels x 2 conv rows x 6 cols, f32x2 over image pair ----
        ull a00[6], a01[6], a10[6], a11[6];   // [ch][convrow][x]
        #pragma unroll
        for (int x = 0; x < 6; ++x) { a00[x]=0; a01[x]=0; a10[x]=0; a11[x]=0; }

        const ull* __restrict__ w0 = (const ull*)(s_wcpf2 + (c0    ) * 25);
        const ull* __restrict__ w1 = (const ull*)(s_wcpf2 + (c0 + 1) * 25);

        #pragma unroll
        for (int ir = 0; ir < 6; ++ir) {
            ull r_[10];
            const ulonglong2* rp = (const ulonglong2*)(ipbase + ir * 28);
            #pragma unroll
            for (int q = 0; q < 5; ++q) {
                ulonglong2 v = rp[q];
                r_[2*q] = v.x; r_[2*q+1] = v.y;
            }
            if (ir < 5) {   // weight row ir -> conv row 0
                #pragma unroll
                for (int kc = 0; kc < 5; ++kc) {
                    ull wv0 = w0[ir * 5 + kc];
                    ull wv1 = w1[ir * 5 + kc];
                    #pragma unroll
                    for (int x = 0; x < 6; ++x) {
                        FMA2(a00[x], r_[x + kc], wv0);
                        FMA2(a10[x], r_[x + kc], wv1);
                    }
                }
            }
            if (ir > 0) {   // weight row ir-1 -> conv row 1
                #pragma unroll
                for (int kc = 0; kc < 5; ++kc) {
                    ull wv0 = w0[(ir - 1) * 5 + kc];
                    ull wv1 = w1[(ir - 1) * 5 + kc];
                    #pragma unroll
                    for (int x = 0; x < 6; ++x) {
                        FMA2(a01[x], r_[x + kc], wv0);
                        FMA2(a11[x], r_[x + kc], wv1);
                    }
                }
            }
        }

        // ---- Pool 2x2 + bias + ReLU (scalar per lane) ----
        {
            float bc0 = s_bias[c0], bc1 = s_bias[c0 + 1];
            float2* pp0 = s_poolf2 + pair * POOL_STR +       prow * 12 + quart * 3;
            float2* pp1 = pp0 + 144;
            #pragma unroll
            for (int px = 0; px < 3; ++px) {
                float2 v0 = u2f(a00[2*px]), v1 = u2f(a00[2*px+1]);
                float2 v2 = u2f(a01[2*px]), v3 = u2f(a01[2*px+1]);
                float mx = fmaxf(fmaxf(v0.x, v1.x), fmaxf(v2.x, v3.x));
                float my = fmaxf(fmaxf(v0.y, v1.y), fmaxf(v2.y, v3.y));
                pp0[px] = make_float2(fmaxf(mx + bc0, 0.f), fmaxf(my + bc0, 0.f));
                float2 u0 = u2f(a10[2*px]), u1 = u2f(a10[2*px+1]);
                float2 u2 = u2f(a11[2*px]), u3 = u2f(a11[2*px+1]);
                float nx = fmaxf(fmaxf(u0.x, u1.x), fmaxf(u2.x, u3.x));
                float ny = fmaxf(fmaxf(u0.y, u1.y), fmaxf(u2.y, u3.y));
                pp1[px] = make_float2(fmaxf(nx + bc1, 0.f), fmaxf(ny + bc1, 0.f));
            }
        }
        __syncthreads();   // pool + wd staged

        // ---- Dense partial: f32x2 accum over image pair, 2 outputs, k-quarter ----
        if (t < 160) {
            const ulonglong2* __restrict__ pl =
                (const ulonglong2*)(s_poolf2 + dpair * POOL_STR + dks * 72);
            const ulonglong2* __restrict__ wa =
                (const ulonglong2*)(s_wdpf2 + (2 * dop    ) * WD_STR + dks * 72);
            const ulonglong2* __restrict__ wb =
                (const ulonglong2*)(s_wdpf2 + (2 * dop + 1) * WD_STR + dks * 72);
            #pragma unroll
            for (int j = 0; j < 36; ++j) {
                ulonglong2 p = pl[j];
                ulonglong2 a = wa[j];
                ulonglong2 b = wb[j];
                FMA2(dacc0a, p.x, a.x);
                FMA2(dacc0b, p.y, a.y);
                FMA2(dacc1a, p.x, b.x);
                FMA2(dacc1b, p.y, b.y);
            }
        }
        __syncthreads();   // dense reads done before next channel overwrites
    }

    // ---- Reduce k-quarters, add bias, log_softmax ----
    if (t < 160) {
        float2 f0 = u2f(dacc0a), f1 = u2f(dacc0b);
        s_redf2[(dpair * 10 + 2 * dop    ) * 4 + dks] = make_float2(f0.x + f1.x, f0.y + f1.y);
        float2 g0 = u2f(dacc1a), g1 = u2f(dacc1b);
        s_redf2[(dpair * 10 + 2 * dop + 1) * 4 + dks] = make_float2(g0.x + g1.x, g0.y + g1.y);
    }
    __syncthreads();

    if (t < 80) {
        int pr = t / 10, o = t % 10;
        float2 s0 = s_redf2[(pr * 10 + o) * 4 + 0];
        float2 s1 = s_redf2[(pr * 10 + o) * 4 + 1];
        float2 s2 = s_redf2[(pr * 10 + o) * 4 + 2];
        float2 s3 = s_redf2[(pr * 10 + o) * 4 + 3];
        float b = P[OFF_BDENSE + o];
        s_log[(2 * pr    ) * 10 + o] = (s0.x + s1.x) + (s2.x + s3.x) + b;
        s_log[(2 * pr + 1) * 10 + o] = (s0.y + s1.y) + (s2.y + s3.y) + b;
    }
    __syncthreads();

    if (t < TILE) {
        float v[10];
        float m = -1e30f;
        #pragma unroll
        for (int o = 0; o < 10; ++o) { v[o] = s_log[t * 10 + o]; m = fmaxf(m, v[o]); }
        float s = 0.f;
        #pragma unroll
        for (int o = 0; o < 10; ++o) s += expf(v[o] - m);
        float ls = m + logf(s);
        float* op = out + ((size_t)init * NBATCH + n0 + t) * 10;
        #pragma unroll
        for (int o = 0; o < 10; ++o) op[o] = v[o] - ls;
    }
}

extern "C" void kernel_launch(void* const* d_in, const int* in_sizes, int n_in,
                              void* d_out, int out_size)
{
    const float* params = (const float*)d_in[0];   // [64, 46922]
    const float* batch  = (const float*)d_in[1];   // [128, 1, 28, 28]
    float* out          = (float*)d_out;           // [64, 128, 10]

    cudaFuncSetAttribute(fused_paramevaler_kernel,
                         cudaFuncAttributeMaxDynamicSharedMemorySize, SMEM_BYTES);

    dim3 grid(NUM_INITS * NTILES);   // 512
    dim3 block(THREADS);             // 384
    fused_paramevaler_kernel<<<grid, block, SMEM_BYTES>>>(params, batch, out);
}

// round 3
// speedup vs baseline: 1.4787x; 1.4787x over previous
#include <cuda_runtime.h>
#include <math.h>

#define NUM_INITS 64
#define PSTRIDE   46922
#define NBATCH    128
#define TILE      16
#define NTILES    8
#define THREADS   384

#define OFF_WDENSE 832
#define OFF_BDENSE 46912

// ---- shared memory layout (float offsets) ----
#define SM_IMG   0            // 16 * 784 = 12544
#define SM_WC    12544        // 32 ch * 40 (5 rows padded to 8 floats) = 1280
#define SM_BIAS  13824        // 32
#define SM_POOL  13856        // 2 bufs * 16 img * 148 = 4736
#define SM_WD    18592        // 3 bufs * 10 out * 148 = 4440
#define SM_RED   23032        // 320
#define SM_LOG   23352        // 160
#define SM_FLOATS 23512
#define SMEM_BYTES (SM_FLOATS * 4)   // 94048 B -> 2 blocks/SM

#define POOL_BUF 2368         // 16*148
#define WD_BUF   1480         // 10*148

__global__ void __launch_bounds__(THREADS, 2)
fused_paramevaler_kernel(const float* __restrict__ params,
                         const float* __restrict__ batch,
                         float* __restrict__ out)
{
    extern __shared__ float sm[];
    float* s_img  = sm + SM_IMG;
    float* s_wc   = sm + SM_WC;
    float* s_bias = sm + SM_BIAS;
    float* s_pool = sm + SM_POOL;
    float* s_wd   = sm + SM_WD;
    float* s_red  = sm + SM_RED;
    float* s_log  = sm + SM_LOG;

    const int blk  = blockIdx.x;
    const int init = blk >> 3;
    const int n0   = (blk & (NTILES - 1)) * TILE;
    const int t    = threadIdx.x;

    const float* __restrict__ P = params + (size_t)init * PSTRIDE;

    // ---- Stage images (coalesced float4) ----
    {
        const float4* __restrict__ src = (const float4*)(batch + (size_t)n0 * 784);
        float4* dst = (float4*)s_img;
        #pragma unroll 1
        for (int k = t; k < TILE * 784 / 4; k += THREADS) dst[k] = src[k];
    }
    // ---- Stage conv weights, rows padded 5->8 floats (16B-aligned rows) ----
    #pragma unroll 1
    for (int u = t; u < 1280; u += THREADS) {
        int c = u / 40, k = u - c * 40;
        int r = k >> 3, q = k & 7;
        s_wc[u] = (r < 5 && q < 5) ? P[c * 25 + r * 5 + q] : 0.f;
    }
    if (t < 32) s_bias[t] = P[800 + t];
    // ---- Stage dense weights for channel 0 into wd buf 0 ----
    #pragma unroll 1
    for (int u = t; u < 720; u += THREADS) {
        int o = u / 72, j = u - o * 72;
        float2 w = *(const float2*)(P + OFF_WDENSE + (size_t)o * 4608 + 2 * j);
        *(float2*)(s_wd + o * 148 + 2 * j) = w;
    }
    __syncthreads();

    // Conv role: (img, pooled row, half) -> 384 threads
    const int img  = t / 24;
    const int rh   = t % 24;
    const int prow = rh >> 1;
    const int half = rh & 1;
    const float* __restrict__ ip = s_img + img * 784 + prow * 56 + half * 12;

    // Dense role: t<320 -> (img, out, k-half)
    const bool dact = (t < 320);
    const int  dn   = t / 20;
    const int  drem = t % 20;
    const int  dob  = drem >> 1;
    const int  dk   = drem & 1;

    #pragma unroll 1
    for (int c = 0; c < 32; ++c) {
        // ---- Stage dense weights for channel c+1 into buf (c+1)%3 ----
        if (c < 31) {
            float* dst = s_wd + ((c + 1) % 3) * WD_BUF;
            #pragma unroll 1
            for (int u = t; u < 720; u += THREADS) {
                int o = u / 72, j = u - o * 72;
                float2 w = *(const float2*)(P + OFF_WDENSE + (size_t)o * 4608
                                            + (c + 1) * 144 + 2 * j);
                *(float2*)(dst + o * 148 + 2 * j) = w;
            }
        }

        // ---- Conv: 2 conv rows x 12 cols ----
        const float* __restrict__ wb = s_wc + c * 40;
        float c0[12], c1[12];
        #pragma unroll
        for (int x = 0; x < 12; ++x) { c0[x] = 0.f; c1[x] = 0.f; }

        #pragma unroll
        for (int ir = 0; ir < 6; ++ir) {
            float r_[16];
            const float4* rp = (const float4*)(ip + ir * 28);
            #pragma unroll
            for (int q = 0; q < 4; ++q) {
                float4 v = rp[q];
                r_[4*q] = v.x; r_[4*q+1] = v.y; r_[4*q+2] = v.z; r_[4*q+3] = v.w;
            }
            if (ir < 5) {   // weight row ir -> conv row 0
                float4 wa = *(const float4*)(wb + ir * 8);
                float  w4 = wb[ir * 8 + 4];
                #pragma unroll
                for (int x = 0; x < 12; ++x)
                    c0[x] = fmaf(r_[x], wa.x, fmaf(r_[x+1], wa.y,
                            fmaf(r_[x+2], wa.z, fmaf(r_[x+3], wa.w,
                            fmaf(r_[x+4], w4, c0[x])))));
            }
            if (ir > 0) {   // weight row ir-1 -> conv row 1
                float4 wa = *(const float4*)(wb + (ir - 1) * 8);
                float  w4 = wb[(ir - 1) * 8 + 4];
                #pragma unroll
                for (int x = 0; x < 12; ++x)
                    c1[x] = fmaf(r_[x], wa.x, fmaf(r_[x+1], wa.y,
                            fmaf(r_[x+2], wa.z, fmaf(r_[x+3], wa.w,
                            fmaf(r_[x+4], w4, c1[x])))));
            }
        }

        // ---- Pool 2x2 + bias + ReLU ----
        {
            float bc = s_bias[c];
            float* pp = s_pool + (c & 1) * POOL_BUF + img * 148 + prow * 12 + half * 6;
            #pragma unroll
            for (int px = 0; px < 6; ++px) {
                float m = fmaxf(fmaxf(c0[2*px], c0[2*px+1]),
                                fmaxf(c1[2*px], c1[2*px+1]));
                pp[px] = fmaxf(m + bc, 0.f);
            }
        }
        __syncthreads();   // pool[c] visible; wd[(c+1)%3] staged

        // ---- Dense partial for channel c (320 threads) ----
        if (dact) {
            const float4* __restrict__ pl =
                (const float4*)(s_pool + (c & 1) * POOL_BUF + dn * 148 + dk * 72);
            const float4* __restrict__ wr =
                (const float4*)(s_wd + (c % 3) * WD_BUF + dob * 148 + dk * 72);
            float a0 = 0.f, a1 = 0.f;
            #pragma unroll
            for (int j = 0; j < 9; ++j) {
                float4 p0 = pl[2*j],     w0 = wr[2*j];
                float4 p1 = pl[2*j + 1], w1 = wr[2*j + 1];
                a0 = fmaf(p0.x, w0.x, fmaf(p0.y, w0.y,
                     fmaf(p0.z, w0.z, fmaf(p0.w, w0.w, a0))));
                a1 = fmaf(p1.x, w1.x, fmaf(p1.y, w1.y,
                     fmaf(p1.z, w1.z, fmaf(p1.w, w1.w, a1))));
            }
            if (c == 0) { s_red[(dn * 10 + dob) * 2 + dk] = a0 + a1; }
            else        { s_red[(dn * 10 + dob) * 2 + dk] += a0 + a1; }
        }
        // no second barrier: next iter's conv writes pool[(c+1)&1] (other buf),
        // next wd staging hits buf (c+2)%3 != (c)%3 read here.
    }
    __syncthreads();

    // ---- bias + log_softmax ----
    if (t < 160) {
        int nn = t / 10, o = t % 10;
        float v = s_red[(nn * 10 + o) * 2] + s_red[(nn * 10 + o) * 2 + 1]
                + P[OFF_BDENSE + o];
        s_log[nn * 10 + o] = v;
    }
    __syncthreads();

    if (t < TILE) {
        float v[10];
        float m = -1e30f;
        #pragma unroll
        for (int o = 0; o < 10; ++o) { v[o] = s_log[t * 10 + o]; m = fmaxf(m, v[o]); }
        float s = 0.f;
        #pragma unroll
        for (int o = 0; o < 10; ++o) s += expf(v[o] - m);
        float ls = m + logf(s);
        float* op = out + ((size_t)init * NBATCH + n0 + t) * 10;
        #pragma unroll
        for (int o = 0; o < 10; ++o) op[o] = v[o] - ls;
    }
}

extern "C" void kernel_launch(void* const* d_in, const int* in_sizes, int n_in,
                              void* d_out, int out_size)
{
    const float* params = (const float*)d_in[0];   // [64, 46922]
    const float* batch  = (const float*)d_in[1];   // [128, 1, 28, 28]
    float* out          = (float*)d_out;           // [64, 128, 10]

    cudaFuncSetAttribute(fused_paramevaler_kernel,
                         cudaFuncAttributeMaxDynamicSharedMemorySize, SMEM_BYTES);

    dim3 grid(NUM_INITS * NTILES);   // 512
    dim3 block(THREADS);             // 384
    fused_paramevaler_kernel<<<grid, block, SMEM_BYTES>>>(params, batch, out);
}

// round 5
// speedup vs baseline: 1.5976x; 1.0804x over previous
#include <cuda_runtime.h>
#include <math.h>

#define NUM_INITS 64
#define PSTRIDE   46922
#define NBATCH    128
#define TILE      16
#define NTILES    8
#define THREADS   384

#define OFF_WDENSE 832
#define OFF_BDENSE 46912

// ---- shared memory layout (float offsets) ----
#define SM_IMG   0            // 16 * 784 = 12544
#define SM_WC    12544        // 32 ch * 40 (5 rows padded to 8) = 1280
#define SM_BIAS  13824        // 32
#define SM_POOL  13856        // 2 bufs * 16 img * 148 = 4736
#define SM_WD    18592        // 3 bufs * 10 out * 148 = 4440
#define SM_RED   23032        // 320
#define SM_LOG   23352        // 160
#define SM_FLOATS 23512
#define SMEM_BYTES (SM_FLOATS * 4)   // 94048 B -> 2 blocks/SM

#define POOL_BUF 2368         // 16*148
#define WD_BUF   1480         // 10*148

__global__ void __launch_bounds__(THREADS, 2)
fused_paramevaler_kernel(const float* __restrict__ params,
                         const float* __restrict__ batch,
                         float* __restrict__ out)
{
    extern __shared__ float sm[];
    float* s_img  = sm + SM_IMG;
    float* s_wc   = sm + SM_WC;
    float* s_bias = sm + SM_BIAS;
    float* s_pool = sm + SM_POOL;
    float* s_wd   = sm + SM_WD;
    float* s_red  = sm + SM_RED;
    float* s_log  = sm + SM_LOG;

    const int blk  = blockIdx.x;
    const int init = blk >> 3;
    const int n0   = (blk & (NTILES - 1)) * TILE;
    const int t    = threadIdx.x;

    const float* __restrict__ P = params + (size_t)init * PSTRIDE;

    // ---- Stage images (coalesced float4) ----
    {
        const float4* __restrict__ src = (const float4*)(batch + (size_t)n0 * 784);
        float4* dst = (float4*)s_img;
        #pragma unroll 1
        for (int k = t; k < TILE * 784 / 4; k += THREADS) dst[k] = src[k];
    }
    // ---- Stage conv weights, rows padded 5->8 floats ----
    #pragma unroll 1
    for (int u = t; u < 1280; u += THREADS) {
        int c = u / 40, k = u - c * 40;
        int r = k >> 3, q = k & 7;
        s_wc[u] = (r < 5 && q < 5) ? P[c * 25 + r * 5 + q] : 0.f;
    }
    if (t < 32) s_bias[t] = P[800 + t];

    // Staging role: t<360 -> (out o, float4-slot q) : 4 floats of wd per thread
    const bool sact = (t < 360);
    const int  so   = t / 36;
    const int  sq   = t - so * 36;
    const float* __restrict__ wsrc = P + OFF_WDENSE + (size_t)so * 4608 + sq * 4;

    // ---- Stage dense weights for channel 0 into wd buf 0 ----
    if (sact) {
        float2 a = *(const float2*)(wsrc);
        float2 b = *(const float2*)(wsrc + 2);
        *(float4*)(s_wd + so * 148 + sq * 4) = make_float4(a.x, a.y, b.x, b.y);
    }
    __syncthreads();

    // Conv role: (img, pooled row, half) -> 384 threads
    const int img  = t / 24;
    const int rh   = t % 24;
    const int prow = rh >> 1;
    const int half = rh & 1;
    const float* __restrict__ ip = s_img + img * 784 + prow * 56 + half * 12;

    // Dense role: t<320 -> (img, out, k-half); accumulators live across channels
    const bool dact = (t < 320);
    const int  dn   = t / 20;
    const int  drem = t % 20;
    const int  dob  = drem >> 1;
    const int  dk   = drem & 1;
    float racc0 = 0.f, racc1 = 0.f;

    #pragma unroll 1
    for (int c = 0; c < 32; ++c) {
        // ---- Prefetch wd[c+1] gmem -> registers (no dependent store yet) ----
        float4 wreg;
        if (c < 31 && sact) {
            float2 a = *(const float2*)(wsrc + (c + 1) * 144);
            float2 b = *(const float2*)(wsrc + (c + 1) * 144 + 2);
            wreg = make_float4(a.x, a.y, b.x, b.y);
        }

        // ---- Conv: 2 conv rows x 12 cols (hides the LDG latency above) ----
        const float* __restrict__ wb = s_wc + c * 40;
        float c0[12], c1[12];
        #pragma unroll
        for (int x = 0; x < 12; ++x) { c0[x] = 0.f; c1[x] = 0.f; }

        #pragma unroll
        for (int ir = 0; ir < 6; ++ir) {
            float r_[16];
            const float4* rp = (const float4*)(ip + ir * 28);
            #pragma unroll
            for (int q = 0; q < 4; ++q) {
                float4 v = rp[q];
                r_[4*q] = v.x; r_[4*q+1] = v.y; r_[4*q+2] = v.z; r_[4*q+3] = v.w;
            }
            if (ir < 5) {
                float4 wa = *(const float4*)(wb + ir * 8);
                float  w4 = wb[ir * 8 + 4];
                #pragma unroll
                for (int x = 0; x < 12; ++x)
                    c0[x] = fmaf(r_[x], wa.x, fmaf(r_[x+1], wa.y,
                            fmaf(r_[x+2], wa.z, fmaf(r_[x+3], wa.w,
                            fmaf(r_[x+4], w4, c0[x])))));
            }
            if (ir > 0) {
                float4 wa = *(const float4*)(wb + (ir - 1) * 8);
                float  w4 = wb[(ir - 1) * 8 + 4];
                #pragma unroll
                for (int x = 0; x < 12; ++x)
                    c1[x] = fmaf(r_[x], wa.x, fmaf(r_[x+1], wa.y,
                            fmaf(r_[x+2], wa.z, fmaf(r_[x+3], wa.w,
                            fmaf(r_[x+4], w4, c1[x])))));
            }
        }

        // ---- Commit prefetched wd[c+1] into buf (c+1)%3 ----
        // (triple buffer: this write shares a barrier interval with dense(c-1),
        //  which reads buf (c-1)%3; (c+1)-(c-1)=2, not 0 mod 3 -> disjoint)
        if (c < 31 && sact)
            *(float4*)(s_wd + ((c + 1) % 3) * WD_BUF + so * 148 + sq * 4) = wreg;

        // ---- Pool 2x2 + bias + ReLU into pool buf c&1 ----
        {
            float bc = s_bias[c];
            float* pp = s_pool + (c & 1) * POOL_BUF + img * 148 + prow * 12 + half * 6;
            #pragma unroll
            for (int px = 0; px < 6; ++px) {
                float m = fmaxf(fmaxf(c0[2*px], c0[2*px+1]),
                                fmaxf(c1[2*px], c1[2*px+1]));
                pp[px] = fmaxf(m + bc, 0.f);
            }
        }
        __syncthreads();   // pool[c] + wd[c+1] visible

        // ---- Dense partial for channel c (320 threads, reg accumulators) ----
        if (dact) {
            const float4* __restrict__ pl =
                (const float4*)(s_pool + (c & 1) * POOL_BUF + dn * 148 + dk * 72);
            const float4* __restrict__ wr =
                (const float4*)(s_wd + (c % 3) * WD_BUF + dob * 148 + dk * 72);
            float a0 = 0.f, a1 = 0.f;
            #pragma unroll
            for (int j = 0; j < 9; ++j) {
                float4 p0 = pl[2*j],     w0 = wr[2*j];
                float4 p1 = pl[2*j + 1], w1 = wr[2*j + 1];
                a0 = fmaf(p0.x, w0.x, fmaf(p0.y, w0.y,
                     fmaf(p0.z, w0.z, fmaf(p0.w, w0.w, a0))));
                a1 = fmaf(p1.x, w1.x, fmaf(p1.y, w1.y,
                     fmaf(p1.z, w1.z, fmaf(p1.w, w1.w, a1))));
            }
            racc0 += a0;
            racc1 += a1;
        }
    }

    // ---- Reduce k-halves, bias, log_softmax ----
    if (dact) s_red[t] = racc0 + racc1;     // t == (dn*10+dob)*2 + dk
    __syncthreads();

    if (t < 160) {
        int nn = t / 10, o = t % 10;
        s_log[t] = s_red[t * 2] + s_red[t * 2 + 1] + P[OFF_BDENSE + o];
    }
    __syncthreads();

    if (t < TILE) {
        float v[10];
        float m = -1e30f;
        #pragma unroll
        for (int o = 0; o < 10; ++o) { v[o] = s_log[t * 10 + o]; m = fmaxf(m, v[o]); }
        float s = 0.f;
        #pragma unroll
        for (int o = 0; o < 10; ++o) s += expf(v[o] - m);
        float ls = m + logf(s);
        float* op = out + ((size_t)init * NBATCH + n0 + t) * 10;
        #pragma unroll
        for (int o = 0; o < 10; ++o) op[o] = v[o] - ls;
    }
}

extern "C" void kernel_launch(void* const* d_in, const int* in_sizes, int n_in,
                              void* d_out, int out_size)
{
    const float* params = (const float*)d_in[0];   // [64, 46922]
    const float* batch  = (const float*)d_in[1];   // [128, 1, 28, 28]
    float* out          = (float*)d_out;           // [64, 128, 10]

    cudaFuncSetAttribute(fused_paramevaler_kernel,
                         cudaFuncAttributeMaxDynamicSharedMemorySize, SMEM_BYTES);

    dim3 grid(NUM_INITS * NTILES);   // 512
    dim3 block(THREADS);             // 384
    fused_paramevaler_kernel<<<grid, block, SMEM_BYTES>>>(params, batch, out);
}

// round 6
// speedup vs baseline: 1.8466x; 1.1559x over previous
#include <cuda_runtime.h>
#include <math.h>

#define NUM_INITS 64
#define PSTRIDE   46922
#define OFF_WDENSE 832
#define OFF_BDENSE 46912

// ---------------- scratch: pooled activations [init][ch*144+w][img=128] ----
__device__ float g_pooled[(size_t)NUM_INITS * 4608 * 128];

// ---------------- tf32 helpers ----------------
__device__ __forceinline__ unsigned tf32_of(float x) {
    unsigned r;
    asm("cvt.rna.tf32.f32 %0, %1;" : "=r"(r) : "f"(x));
    return r;
}

#define MMA_TF32(c0,c1,c2,c3,a0,a1,a2,a3,b0,b1) \
    asm("mma.sync.aligned.m16n8k8.row.col.f32.tf32.tf32.f32 " \
        "{%0,%1,%2,%3}, {%4,%5,%6,%7}, {%8,%9}, {%0,%1,%2,%3};" \
        : "+f"(c0), "+f"(c1), "+f"(c2), "+f"(c3) \
        : "r"(a0), "r"(a1), "r"(a2), "r"(a3), "r"(b0), "r"(b1))

// ============================================================================
// Kernel 1: conv 5x5 + pool 2x2 + bias + relu  (tensor cores, tf32 3-pass)
// grid 512 = (init, img-tile of 16), 384 threads = 12 warps
// warp -> (warpgroup wg: ch 16*wg..+15, window group widx: windows widx*24..+23)
// ============================================================================
#define IMG_STR 788                       // 784 + 4 pad (788 % 32 == 20)
#define K1_THREADS 384
#define K1_SMEM (16 * IMG_STR * 4)        // 50432 B

__global__ void __launch_bounds__(K1_THREADS, 2)
conv_pool_kernel(const float* __restrict__ params,
                 const float* __restrict__ batch)
{
    extern __shared__ float s_img[];

    const int blk  = blockIdx.x;
    const int init = blk >> 3;
    const int n0   = (blk & 7) * 16;
    const int t    = threadIdx.x;
    const int warp = t >> 5;
    const int lane = t & 31;
    const int g    = lane >> 2;   // 0..7
    const int tid  = lane & 3;    // 0..3

    const float* __restrict__ P = params + (size_t)init * PSTRIDE;

    // ---- stage 16 images, stride padded to 788 floats ----
    for (int u = t; u < 16 * 196; u += K1_THREADS) {
        int img = u / 196, q = u - img * 196;
        ((float4*)(s_img + img * IMG_STR))[q] =
            ((const float4*)(batch + (size_t)(n0 + img) * 784))[q];
    }
    __syncthreads();

    const int wg     = warp / 6;          // 0,1 -> channels wg*16 .. +15
    const int widx   = warp % 6;          // windows widx*24 .. +23
    const int chbase = wg * 16;

    // ---- B fragments (weights), split hi/lo: [ntile][kstep][reg] ----
    unsigned bhi[2][3][2], blo[2][3][2];
    #pragma unroll
    for (int nt = 0; nt < 2; ++nt) {
        int ch = chbase + nt * 8 + g;
        #pragma unroll
        for (int s = 0; s < 3; ++s) {
            float w0 = P[ch * 25 + s * 8 + tid];
            float w1 = P[ch * 25 + s * 8 + tid + 4];
            unsigned h0 = tf32_of(w0), h1 = tf32_of(w1);
            bhi[nt][s][0] = h0;
            bhi[nt][s][1] = h1;
            blo[nt][s][0] = tf32_of(w0 - __uint_as_float(h0));
            blo[nt][s][1] = tf32_of(w1 - __uint_as_float(h1));
        }
    }
    // ---- tap-24 weights + bias for this thread's C columns (2tid, 2tid+1) --
    float w24[2][2], cbias[2][2];
    #pragma unroll
    for (int nt = 0; nt < 2; ++nt)
        #pragma unroll
        for (int jj = 0; jj < 2; ++jj) {
            int ch = chbase + nt * 8 + 2 * tid + jj;
            w24[nt][jj]   = P[ch * 25 + 24];
            cbias[nt][jj] = P[800 + ch];
        }

    // ---- per-thread k offsets into the image (k = ky*5+kx -> ky*28+kx) ----
    int koffA[3], koffB[3];
    #pragma unroll
    for (int s = 0; s < 3; ++s) {
        int ka = s * 8 + tid;
        int kb = ka + 4;
        koffA[s] = (ka / 5) * 28 + (ka % 5);
        koffB[s] = (kb / 5) * 28 + (kb % 5);
    }

    const size_t outbase = (size_t)init * 4608;

    // ---- main loop: 24 pool windows, no further barriers ----
    #pragma unroll 1
    for (int j = 0; j < 24; ++j) {
        int w  = widx * 24 + j;
        int wy = w / 12, wx = w - (w / 12) * 12;

        float pc[2][4];                   // pooled C frags per ntile

        #pragma unroll
        for (int p = 0; p < 4; ++p) {
            int y = 2 * wy + (p >> 1);
            int x = 2 * wx + (p & 1);
            int base0 = g * IMG_STR + y * 28 + x;
            int base1 = base0 + 8 * IMG_STR;

            // C initialized with the k=24 fixup (full fp32)
            float v0 = s_img[base0 + 116];     // img row g,  (y+4, x+4)
            float v1 = s_img[base1 + 116];     // img row g+8
            float c[2][4];
            #pragma unroll
            for (int nt = 0; nt < 2; ++nt) {
                c[nt][0] = v0 * w24[nt][0];
                c[nt][1] = v0 * w24[nt][1];
                c[nt][2] = v1 * w24[nt][0];
                c[nt][3] = v1 * w24[nt][1];
            }

            #pragma unroll
            for (int s = 0; s < 3; ++s) {
                float a0f = s_img[base0 + koffA[s]];
                float a1f = s_img[base1 + koffA[s]];
                float a2f = s_img[base0 + koffB[s]];
                float a3f = s_img[base1 + koffB[s]];
                unsigned ah0 = tf32_of(a0f), ah1 = tf32_of(a1f);
                unsigned ah2 = tf32_of(a2f), ah3 = tf32_of(a3f);
                unsigned al0 = tf32_of(a0f - __uint_as_float(ah0));
                unsigned al1 = tf32_of(a1f - __uint_as_float(ah1));
                unsigned al2 = tf32_of(a2f - __uint_as_float(ah2));
                unsigned al3 = tf32_of(a3f - __uint_as_float(ah3));
                #pragma unroll
                for (int nt = 0; nt < 2; ++nt) {
                    MMA_TF32(c[nt][0], c[nt][1], c[nt][2], c[nt][3],
                             ah0, ah1, ah2, ah3,
                             bhi[nt][s][0], bhi[nt][s][1]);
                    MMA_TF32(c[nt][0], c[nt][1], c[nt][2], c[nt][3],
                             ah0, ah1, ah2, ah3,
                             blo[nt][s][0], blo[nt][s][1]);
                    MMA_TF32(c[nt][0], c[nt][1], c[nt][2], c[nt][3],
                             al0, al1, al2, al3,
                             bhi[nt][s][0], bhi[nt][s][1]);
                }
            }

            if (p == 0) {
                #pragma unroll
                for (int nt = 0; nt < 2; ++nt)
                    #pragma unroll
                    for (int e = 0; e < 4; ++e) pc[nt][e] = c[nt][e];
            } else {
                #pragma unroll
                for (int nt = 0; nt < 2; ++nt)
                    #pragma unroll
                    for (int e = 0; e < 4; ++e)
                        pc[nt][e] = fmaxf(pc[nt][e], c[nt][e]);
            }
        }

        // bias + relu + store:  g_pooled[init][ch][w][n0+img]
        #pragma unroll
        for (int nt = 0; nt < 2; ++nt) {
            #pragma unroll
            for (int e = 0; e < 4; ++e) {
                int ch  = chbase + nt * 8 + 2 * tid + (e & 1);
                int img = (e < 2) ? g : (g + 8);
                float v = fmaxf(pc[nt][e] + cbias[nt][e & 1], 0.f);
                g_pooled[(outbase + (size_t)ch * 144 + w) * 128 + n0 + img] = v;
            }
        }
    }
}

// ============================================================================
// Kernel 2: dense [128 x 4608] x [4608 x 10] + bias + log_softmax, per init
// grid 256 = (init, img-quarter of 32), 256 threads
// thread = (slice 0..31 of k, imggrp 0..3, oh 0..1) -> 8 img x 5 out reg tile
// ============================================================================
#define K2_THREADS 256

__global__ void __launch_bounds__(K2_THREADS)
dense_softmax_kernel(const float* __restrict__ params,
                     float* __restrict__ out)
{
    __shared__ float s_red[320 * 33];
    __shared__ float s_log[320];

    const int blk    = blockIdx.x;       // 0..255
    const int init   = blk >> 2;
    const int imgq   = blk & 3;
    const int t      = threadIdx.x;
    const int slice  = t >> 3;           // 0..31
    const int role   = t & 7;
    const int imggrp = role & 3;         // 0..3
    const int oh     = role >> 2;        // 0..1

    const float* __restrict__ P = params + (size_t)init * PSTRIDE;
    const float4* __restrict__ pool4 =
        (const float4*)(g_pooled + (size_t)init * 4608 * 128);
    const float* __restrict__ wdp = P + OFF_WDENSE + (size_t)(oh * 5) * 4608;

    float acc[5][8];
    #pragma unroll
    for (int oi = 0; oi < 5; ++oi)
        #pragma unroll
        for (int im = 0; im < 8; ++im) acc[oi][im] = 0.f;

    const int pbase = imgq * 8 + imggrp * 2;
    const int kbase = slice * 144;

    #pragma unroll 1
    for (int kk = 0; kk < 144; kk += 2) {
        int k = kbase + kk;
        float4 p00 = pool4[(size_t)k * 32 + pbase];
        float4 p01 = pool4[(size_t)k * 32 + pbase + 1];
        float4 p10 = pool4[(size_t)(k + 1) * 32 + pbase];
        float4 p11 = pool4[(size_t)(k + 1) * 32 + pbase + 1];
        #pragma unroll
        for (int oi = 0; oi < 5; ++oi) {
            float2 w = *(const float2*)(wdp + (size_t)oi * 4608 + k);
            acc[oi][0] = fmaf(p00.x, w.x, fmaf(p10.x, w.y, acc[oi][0]));
            acc[oi][1] = fmaf(p00.y, w.x, fmaf(p10.y, w.y, acc[oi][1]));
            acc[oi][2] = fmaf(p00.z, w.x, fmaf(p10.z, w.y, acc[oi][2]));
            acc[oi][3] = fmaf(p00.w, w.x, fmaf(p10.w, w.y, acc[oi][3]));
            acc[oi][4] = fmaf(p01.x, w.x, fmaf(p11.x, w.y, acc[oi][4]));
            acc[oi][5] = fmaf(p01.y, w.x, fmaf(p11.y, w.y, acc[oi][5]));
            acc[oi][6] = fmaf(p01.z, w.x, fmaf(p11.z, w.y, acc[oi][6]));
            acc[oi][7] = fmaf(p01.w, w.x, fmaf(p11.w, w.y, acc[oi][7]));
        }
    }

    // partials -> smem
    #pragma unroll
    for (int oi = 0; oi < 5; ++oi)
        #pragma unroll
        for (int im = 0; im < 8; ++im) {
            int img_l = imggrp * 8 + im;
            int o     = oh * 5 + oi;
            s_red[(img_l * 10 + o) * 33 + slice] = acc[oi][im];
        }
    __syncthreads();

    // reduce 32 slices + dense bias
    for (int slot = t; slot < 320; slot += K2_THREADS) {
        float s = 0.f;
        #pragma unroll
        for (int jj = 0; jj < 32; ++jj) s += s_red[slot * 33 + jj];
        s_log[slot] = s + P[OFF_BDENSE + slot % 10];
    }
    __syncthreads();

    // log_softmax per image
    if (t < 32) {
        float v[10], m = -1e30f;
        #pragma unroll
        for (int o = 0; o < 10; ++o) { v[o] = s_log[t * 10 + o]; m = fmaxf(m, v[o]); }
        float su = 0.f;
        #pragma unroll
        for (int o = 0; o < 10; ++o) su += expf(v[o] - m);
        float ls = m + logf(su);
        float* op = out + ((size_t)init * 128 + imgq * 32 + t) * 10;
        #pragma unroll
        for (int o = 0; o < 10; ++o) op[o] = v[o] - ls;
    }
}

// ============================================================================
extern "C" void kernel_launch(void* const* d_in, const int* in_sizes, int n_in,
                              void* d_out, int out_size)
{
    const float* params = (const float*)d_in[0];   // [64, 46922]
    const float* batch  = (const float*)d_in[1];   // [128, 1, 28, 28]
    float* out          = (float*)d_out;           // [64, 128, 10]

    cudaFuncSetAttribute(conv_pool_kernel,
                         cudaFuncAttributeMaxDynamicSharedMemorySize, K1_SMEM);

    conv_pool_kernel<<<512, K1_THREADS, K1_SMEM>>>(params, batch);
    dense_softmax_kernel<<<256, K2_THREADS>>>(params, out);
}

// round 7
// speedup vs baseline: 2.6416x; 1.4305x over previous
#include <cuda_runtime.h>
#include <cuda_fp16.h>
#include <math.h>

#define NUM_INITS 64
#define PSTRIDE   46922
#define OFF_WDENSE 832
#define OFF_BDENSE 46912

// Dense weights pre-swizzled into fp16 B-fragment order:
// [init][wg(2)][w(144)][lane(32)] -> uint4 {b0_nt0, b1_nt0, b0_nt1, b1_nt1}
__device__ uint4 g_wdh[128 * 144 * 32];   // 9.4 MB

__device__ __forceinline__ unsigned pack_h2(float lo, float hi) {
    __half2 h = __floats2half2_rn(lo, hi);
    return *(unsigned*)&h;
}

__device__ __forceinline__ unsigned tf32_of(float x) {
    unsigned r;
    asm("cvt.rna.tf32.f32 %0, %1;" : "=r"(r) : "f"(x));
    return r;
}

#define MMA_TF32(c0,c1,c2,c3,a0,a1,a2,a3,b0,b1) \
    asm("mma.sync.aligned.m16n8k8.row.col.f32.tf32.tf32.f32 " \
        "{%0,%1,%2,%3}, {%4,%5,%6,%7}, {%8,%9}, {%0,%1,%2,%3};" \
        : "+f"(c0), "+f"(c1), "+f"(c2), "+f"(c3) \
        : "r"(a0), "r"(a1), "r"(a2), "r"(a3), "r"(b0), "r"(b1))

#define MMA_F16(c0,c1,c2,c3,a0,a1,a2,a3,b0,b1) \
    asm("mma.sync.aligned.m16n8k16.row.col.f32.f16.f16.f32 " \
        "{%0,%1,%2,%3}, {%4,%5,%6,%7}, {%8,%9}, {%0,%1,%2,%3};" \
        : "+f"(c0), "+f"(c1), "+f"(c2), "+f"(c3) \
        : "r"(a0), "r"(a1), "r"(a2), "r"(a3), "r"(b0), "r"(b1))

// ============================================================================
// Prep: swizzle dense weights -> fp16 B fragments. grid 128 = (init, wg)
// ============================================================================
__global__ void __launch_bounds__(256)
prep_wd_kernel(const float* __restrict__ params)
{
    const int blk  = blockIdx.x;          // init*2 + wg
    const int init = blk >> 1;
    const int wg   = blk & 1;
    const float* __restrict__ W = params + (size_t)init * PSTRIDE + OFF_WDENSE;

    for (int u = threadIdx.x; u < 144 * 32; u += 256) {
        int w    = u >> 5;
        int lane = u & 31;
        int g    = lane >> 2;
        int tb   = lane & 3;
        int ch0  = wg * 16 + 2 * tb;

        #define WD(o, ch) W[(size_t)(o) * 4608 + (ch) * 144 + w]
        unsigned b0n0 = pack_h2(WD(g, ch0),     WD(g, ch0 + 1));
        unsigned b1n0 = pack_h2(WD(g, ch0 + 8), WD(g, ch0 + 9));
        unsigned b0n1 = 0, b1n1 = 0;
        if (g + 8 < 10) {
            b0n1 = pack_h2(WD(g + 8, ch0),     WD(g + 8, ch0 + 1));
            b1n1 = pack_h2(WD(g + 8, ch0 + 8), WD(g + 8, ch0 + 9));
        }
        #undef WD
        g_wdh[(size_t)(blk * 144 + w) * 32 + lane] =
            make_uint4(b0n0, b1n0, b0n1, b1n1);
    }
}

// ============================================================================
// Fused: conv5x5(tf32 3-pass) + pool + bias + relu + dense(fp16 mma) + softmax
// grid 512 = (init, img-tile of 16), 384 threads = 12 warps
// ============================================================================
#define IMG_STR 788
#define K1_THREADS 384
#define K1_SMEM (16 * IMG_STR * 4)        // 50432 B

__global__ void __launch_bounds__(K1_THREADS, 2)
fused_kernel(const float* __restrict__ params,
             const float* __restrict__ batch,
             float* __restrict__ out)
{
    extern __shared__ float s_img[];

    const int blk  = blockIdx.x;
    const int init = blk >> 3;
    const int n0   = (blk & 7) * 16;
    const int t    = threadIdx.x;
    const int warp = t >> 5;
    const int lane = t & 31;
    const int g    = lane >> 2;   // 0..7
    const int tid  = lane & 3;    // 0..3

    const float* __restrict__ P = params + (size_t)init * PSTRIDE;

    // ---- stage 16 images ----
    for (int u = t; u < 16 * 196; u += K1_THREADS) {
        int img = u / 196, q = u - img * 196;
        ((float4*)(s_img + img * IMG_STR))[q] =
            ((const float4*)(batch + (size_t)(n0 + img) * 784))[q];
    }
    __syncthreads();

    const int wg     = warp / 6;          // channels wg*16..+15
    const int widx   = warp % 6;          // windows widx*24..+23
    const int chbase = wg * 16;

    // ---- conv B fragments (weights), split hi/lo ----
    unsigned bhi[2][3][2], blo[2][3][2];
    #pragma unroll
    for (int nt = 0; nt < 2; ++nt) {
        int ch = chbase + nt * 8 + g;
        #pragma unroll
        for (int s = 0; s < 3; ++s) {
            float w0 = P[ch * 25 + s * 8 + tid];
            float w1 = P[ch * 25 + s * 8 + tid + 4];
            unsigned h0 = tf32_of(w0), h1 = tf32_of(w1);
            bhi[nt][s][0] = h0;
            bhi[nt][s][1] = h1;
            blo[nt][s][0] = tf32_of(w0 - __uint_as_float(h0));
            blo[nt][s][1] = tf32_of(w1 - __uint_as_float(h1));
        }
    }
    float w24[2][2], cbias[2][2];
    #pragma unroll
    for (int nt = 0; nt < 2; ++nt)
        #pragma unroll
        for (int jj = 0; jj < 2; ++jj) {
            int ch = chbase + nt * 8 + 2 * tid + jj;
            w24[nt][jj]   = P[ch * 25 + 24];
            cbias[nt][jj] = P[800 + ch];
        }

    int koffA[3], koffB[3];
    #pragma unroll
    for (int s = 0; s < 3; ++s) {
        int ka = s * 8 + tid, kb = ka + 4;
        koffA[s] = (ka / 5) * 28 + (ka % 5);
        koffB[s] = (kb / 5) * 28 + (kb % 5);
    }

    const uint4* __restrict__ wdfrag =
        g_wdh + (size_t)((init * 2 + wg) * 144) * 32 + lane;

    // persistent dense accumulators: nt_out 0 -> outs 0..7, nt_out 1 -> 8..15
    float dc[2][4];
    #pragma unroll
    for (int q = 0; q < 4; ++q) { dc[0][q] = 0.f; dc[1][q] = 0.f; }

    // ---- main loop over this warp's 24 pool windows ----
    #pragma unroll 1
    for (int j = 0; j < 24; ++j) {
        int w  = widx * 24 + j;
        int wy = w / 12, wx = w - (w / 12) * 12;

        uint4 Bv = wdfrag[(size_t)w * 32];       // dense B frags (L2)

        float pc[2][4];
        #pragma unroll
        for (int p = 0; p < 4; ++p) {
            int y = 2 * wy + (p >> 1);
            int x = 2 * wx + (p & 1);
            int base0 = g * IMG_STR + y * 28 + x;
            int base1 = base0 + 8 * IMG_STR;

            float v0 = s_img[base0 + 116];
            float v1 = s_img[base1 + 116];
            float c[2][4];
            #pragma unroll
            for (int nt = 0; nt < 2; ++nt) {
                c[nt][0] = v0 * w24[nt][0];
                c[nt][1] = v0 * w24[nt][1];
                c[nt][2] = v1 * w24[nt][0];
                c[nt][3] = v1 * w24[nt][1];
            }

            #pragma unroll
            for (int s = 0; s < 3; ++s) {
                float a0f = s_img[base0 + koffA[s]];
                float a1f = s_img[base1 + koffA[s]];
                float a2f = s_img[base0 + koffB[s]];
                float a3f = s_img[base1 + koffB[s]];
                unsigned ah0 = tf32_of(a0f), ah1 = tf32_of(a1f);
                unsigned ah2 = tf32_of(a2f), ah3 = tf32_of(a3f);
                unsigned al0 = tf32_of(a0f - __uint_as_float(ah0));
                unsigned al1 = tf32_of(a1f - __uint_as_float(ah1));
                unsigned al2 = tf32_of(a2f - __uint_as_float(ah2));
                unsigned al3 = tf32_of(a3f - __uint_as_float(ah3));
                #pragma unroll
                for (int nt = 0; nt < 2; ++nt) {
                    MMA_TF32(c[nt][0], c[nt][1], c[nt][2], c[nt][3],
                             ah0, ah1, ah2, ah3,
                             bhi[nt][s][0], bhi[nt][s][1]);
                    MMA_TF32(c[nt][0], c[nt][1], c[nt][2], c[nt][3],
                             ah0, ah1, ah2, ah3,
                             blo[nt][s][0], blo[nt][s][1]);
                    MMA_TF32(c[nt][0], c[nt][1], c[nt][2], c[nt][3],
                             al0, al1, al2, al3,
                             bhi[nt][s][0], bhi[nt][s][1]);
                }
            }

            if (p == 0) {
                #pragma unroll
                for (int nt = 0; nt < 2; ++nt)
                    #pragma unroll
                    for (int e = 0; e < 4; ++e) pc[nt][e] = c[nt][e];
            } else {
                #pragma unroll
                for (int nt = 0; nt < 2; ++nt)
                    #pragma unroll
                    for (int e = 0; e < 4; ++e)
                        pc[nt][e] = fmaxf(pc[nt][e], c[nt][e]);
            }
        }

        // bias + relu in registers
        #pragma unroll
        for (int nt = 0; nt < 2; ++nt) {
            pc[nt][0] = fmaxf(pc[nt][0] + cbias[nt][0], 0.f);
            pc[nt][1] = fmaxf(pc[nt][1] + cbias[nt][1], 0.f);
            pc[nt][2] = fmaxf(pc[nt][2] + cbias[nt][0], 0.f);
            pc[nt][3] = fmaxf(pc[nt][3] + cbias[nt][1], 0.f);
        }

        // pack pooled frags -> fp16 A (16 img x 16 ch), k = ch - chbase
        unsigned a0 = pack_h2(pc[0][0], pc[0][1]);   // (img g,   k 2tid,2tid+1)
        unsigned a1 = pack_h2(pc[0][2], pc[0][3]);   // (img g+8)
        unsigned a2 = pack_h2(pc[1][0], pc[1][1]);   // (img g,   k 8+2tid,..)
        unsigned a3 = pack_h2(pc[1][2], pc[1][3]);

        // dense: outs 0..7 and 8..15 (>=10 are zero-padded in B)
        MMA_F16(dc[0][0], dc[0][1], dc[0][2], dc[0][3],
                a0, a1, a2, a3, Bv.x, Bv.y);
        MMA_F16(dc[1][0], dc[1][1], dc[1][2], dc[1][3],
                a0, a1, a2, a3, Bv.z, Bv.w);
    }

    // ---- reduce 12 warps' partial dense C, bias, log_softmax ----
    __syncthreads();                  // everyone done reading s_img
    float* s_red = s_img;             // [12][16 img][16 out]
    float* s_log = s_img + 12 * 256;  // [16][10]
    {
        float* wr = s_red + warp * 256;
        wr[ g      * 16 + 2 * tid    ] = dc[0][0];
        wr[ g      * 16 + 2 * tid + 1] = dc[0][1];
        wr[(g + 8) * 16 + 2 * tid    ] = dc[0][2];
        wr[(g + 8) * 16 + 2 * tid + 1] = dc[0][3];
        wr[ g      * 16 + 8 + 2 * tid    ] = dc[1][0];
        wr[ g      * 16 + 8 + 2 * tid + 1] = dc[1][1];
        wr[(g + 8) * 16 + 8 + 2 * tid    ] = dc[1][2];
        wr[(g + 8) * 16 + 8 + 2 * tid + 1] = dc[1][3];
    }
    __syncthreads();

    if (t < 160) {
        int img = t / 10, o = t % 10;
        float s = 0.f;
        #pragma unroll
        for (int wp = 0; wp < 12; ++wp) s += s_red[wp * 256 + img * 16 + o];
        s_log[t] = s + P[OFF_BDENSE + o];
    }
    __syncthreads();

    if (t < 16) {
        float v[10], m = -1e30f;
        #pragma unroll
        for (int o = 0; o < 10; ++o) { v[o] = s_log[t * 10 + o]; m = fmaxf(m, v[o]); }
        float su = 0.f;
        #pragma unroll
        for (int o = 0; o < 10; ++o) su += expf(v[o] - m);
        float ls = m + logf(su);
        float* op = out + ((size_t)init * 128 + n0 + t) * 10;
        #pragma unroll
        for (int o = 0; o < 10; ++o) op[o] = v[o] - ls;
    }
}

// ============================================================================
extern "C" void kernel_launch(void* const* d_in, const int* in_sizes, int n_in,
                              void* d_out, int out_size)
{
    const float* params = (const float*)d_in[0];   // [64, 46922]
    const float* batch  = (const float*)d_in[1];   // [128, 1, 28, 28]
    float* out          = (float*)d_out;           // [64, 128, 10]

    cudaFuncSetAttribute(fused_kernel,
                         cudaFuncAttributeMaxDynamicSharedMemorySize, K1_SMEM);

    prep_wd_kernel<<<128, 256>>>(params);
    fused_kernel<<<512, K1_THREADS, K1_SMEM>>>(params, batch, out);
}

// round 8
// speedup vs baseline: 3.2657x; 1.2363x over previous
#include <cuda_runtime.h>
#include <cuda_fp16.h>
#include <math.h>

#define NUM_INITS 64
#define PSTRIDE   46922
#define OFF_WDENSE 832
#define OFF_BDENSE 46912

// Dense weights pre-swizzled into fp16 B-fragment order:
// [init][wg(2)][w(144)][lane(32)] -> uint4 {b0_nt0, b1_nt0, b0_nt1, b1_nt1}
__device__ uint4 g_wdh[128 * 144 * 32];   // 9.4 MB

__device__ __forceinline__ unsigned pack_h2(float lo, float hi) {
    __half2 h = __floats2half2_rn(lo, hi);
    return *(unsigned*)&h;
}

__device__ __forceinline__ unsigned tf32_of(float x) {
    unsigned r;
    asm("cvt.rna.tf32.f32 %0, %1;" : "=r"(r) : "f"(x));
    return r;
}

#define MMA_TF32(c0,c1,c2,c3,a0,a1,a2,a3,b0,b1) \
    asm("mma.sync.aligned.m16n8k8.row.col.f32.tf32.tf32.f32 " \
        "{%0,%1,%2,%3}, {%4,%5,%6,%7}, {%8,%9}, {%0,%1,%2,%3};" \
        : "+f"(c0), "+f"(c1), "+f"(c2), "+f"(c3) \
        : "r"(a0), "r"(a1), "r"(a2), "r"(a3), "r"(b0), "r"(b1))

#define MMA_F16(c0,c1,c2,c3,a0,a1,a2,a3,b0,b1) \
    asm("mma.sync.aligned.m16n8k16.row.col.f32.f16.f16.f32 " \
        "{%0,%1,%2,%3}, {%4,%5,%6,%7}, {%8,%9}, {%0,%1,%2,%3};" \
        : "+f"(c0), "+f"(c1), "+f"(c2), "+f"(c3) \
        : "r"(a0), "r"(a1), "r"(a2), "r"(a3), "r"(b0), "r"(b1))

// ============================================================================
// Prep: swizzle dense weights -> fp16 B fragments. grid 128 = (init, wg)
// ============================================================================
__global__ void __launch_bounds__(256)
prep_wd_kernel(const float* __restrict__ params)
{
    const int blk  = blockIdx.x;          // init*2 + wg
    const int init = blk >> 1;
    const int wg   = blk & 1;
    const float* __restrict__ W = params + (size_t)init * PSTRIDE + OFF_WDENSE;

    for (int u = threadIdx.x; u < 144 * 32; u += 256) {
        int w    = u >> 5;
        int lane = u & 31;
        int g    = lane >> 2;
        int tb   = lane & 3;
        int ch0  = wg * 16 + 2 * tb;

        #define WD(o, ch) W[(size_t)(o) * 4608 + (ch) * 144 + w]
        unsigned b0n0 = pack_h2(WD(g, ch0),     WD(g, ch0 + 1));
        unsigned b1n0 = pack_h2(WD(g, ch0 + 8), WD(g, ch0 + 9));
        unsigned b0n1 = 0, b1n1 = 0;
        if (g + 8 < 10) {
            b0n1 = pack_h2(WD(g + 8, ch0),     WD(g + 8, ch0 + 1));
            b1n1 = pack_h2(WD(g + 8, ch0 + 8), WD(g + 8, ch0 + 9));
        }
        #undef WD
        g_wdh[(size_t)(blk * 144 + w) * 32 + lane] =
            make_uint4(b0n0, b1n0, b0n1, b1n1);
    }
}

// ============================================================================
// Fused: conv5x5(tf32 3-pass, hi/lo precomputed in smem) + pool + bias + relu
//        + dense(fp16 mma) + log_softmax
// grid 512 = (init, img-tile of 16), 384 threads = 12 warps
// ============================================================================
#define IMG_STR 788
#define K1_THREADS 384
#define K1_SMEM (2 * 16 * IMG_STR * 4)    // hi + lo planes = 100864 B

__global__ void __launch_bounds__(K1_THREADS, 2)
fused_kernel(const float* __restrict__ params,
             const float* __restrict__ batch,
             float* __restrict__ out)
{
    extern __shared__ unsigned s_mem[];
    unsigned* s_hi = s_mem;                   // [16][788] tf32 hi bits
    unsigned* s_lo = s_mem + 16 * IMG_STR;    // [16][788] tf32 lo bits

    const int blk  = blockIdx.x;
    const int init = blk >> 3;
    const int n0   = (blk & 7) * 16;
    const int t    = threadIdx.x;
    const int warp = t >> 5;
    const int lane = t & 31;
    const int g    = lane >> 2;   // 0..7
    const int tid  = lane & 3;    // 0..3

    const float* __restrict__ P = params + (size_t)init * PSTRIDE;

    // ---- stage 16 images, splitting each pixel into tf32 hi/lo once ----
    for (int u = t; u < 16 * 196; u += K1_THREADS) {
        int img = u / 196, q = u - img * 196;
        float4 v = ((const float4*)(batch + (size_t)(n0 + img) * 784))[q];
        uint4 hi, lo;
        hi.x = tf32_of(v.x); lo.x = tf32_of(v.x - __uint_as_float(hi.x));
        hi.y = tf32_of(v.y); lo.y = tf32_of(v.y - __uint_as_float(hi.y));
        hi.z = tf32_of(v.z); lo.z = tf32_of(v.z - __uint_as_float(hi.z));
        hi.w = tf32_of(v.w); lo.w = tf32_of(v.w - __uint_as_float(hi.w));
        ((uint4*)(s_hi + img * IMG_STR))[q] = hi;
        ((uint4*)(s_lo + img * IMG_STR))[q] = lo;
    }
    __syncthreads();

    const int wg     = warp / 6;          // channels wg*16..+15
    const int widx   = warp % 6;          // windows widx*24..+23
    const int chbase = wg * 16;

    // ---- conv B fragments (weights), split hi/lo ----
    unsigned bhi[2][3][2], blo[2][3][2];
    #pragma unroll
    for (int nt = 0; nt < 2; ++nt) {
        int ch = chbase + nt * 8 + g;
        #pragma unroll
        for (int s = 0; s < 3; ++s) {
            float w0 = P[ch * 25 + s * 8 + tid];
            float w1 = P[ch * 25 + s * 8 + tid + 4];
            unsigned h0 = tf32_of(w0), h1 = tf32_of(w1);
            bhi[nt][s][0] = h0;
            bhi[nt][s][1] = h1;
            blo[nt][s][0] = tf32_of(w0 - __uint_as_float(h0));
            blo[nt][s][1] = tf32_of(w1 - __uint_as_float(h1));
        }
    }
    float w24[2][2], cbias[2][2];
    #pragma unroll
    for (int nt = 0; nt < 2; ++nt)
        #pragma unroll
        for (int jj = 0; jj < 2; ++jj) {
            int ch = chbase + nt * 8 + 2 * tid + jj;
            w24[nt][jj]   = P[ch * 25 + 24];
            cbias[nt][jj] = P[800 + ch];
        }

    int koffA[3], koffB[3];
    #pragma unroll
    for (int s = 0; s < 3; ++s) {
        int ka = s * 8 + tid, kb = ka + 4;
        koffA[s] = (ka / 5) * 28 + (ka % 5);
        koffB[s] = (kb / 5) * 28 + (kb % 5);
    }

    const uint4* __restrict__ wdfrag =
        g_wdh + (size_t)((init * 2 + wg) * 144) * 32 + lane;

    // persistent dense accumulators
    float dc[2][4];
    #pragma unroll
    for (int q = 0; q < 4; ++q) { dc[0][q] = 0.f; dc[1][q] = 0.f; }

    // ---- main loop over this warp's 24 pool windows ----
    #pragma unroll 1
    for (int j = 0; j < 24; ++j) {
        int w  = widx * 24 + j;
        int wy = w / 12, wx = w - (w / 12) * 12;

        uint4 Bv = wdfrag[(size_t)w * 32];       // dense B frags (L2)

        float pc[2][4];
        #pragma unroll
        for (int p = 0; p < 4; ++p) {
            int y = 2 * wy + (p >> 1);
            int x = 2 * wx + (p & 1);
            int base0 = g * IMG_STR + y * 28 + x;
            int base1 = base0 + 8 * IMG_STR;

            // C initialized with k=24 fixup (hi+lo reconstructs the pixel)
            float v0 = __uint_as_float(s_hi[base0 + 116])
                     + __uint_as_float(s_lo[base0 + 116]);
            float v1 = __uint_as_float(s_hi[base1 + 116])
                     + __uint_as_float(s_lo[base1 + 116]);
            float c[2][4];
            #pragma unroll
            for (int nt = 0; nt < 2; ++nt) {
                c[nt][0] = v0 * w24[nt][0];
                c[nt][1] = v0 * w24[nt][1];
                c[nt][2] = v1 * w24[nt][0];
                c[nt][3] = v1 * w24[nt][1];
            }

            #pragma unroll
            for (int s = 0; s < 3; ++s) {
                unsigned ah0 = s_hi[base0 + koffA[s]];
                unsigned ah1 = s_hi[base1 + koffA[s]];
                unsigned ah2 = s_hi[base0 + koffB[s]];
                unsigned ah3 = s_hi[base1 + koffB[s]];
                unsigned al0 = s_lo[base0 + koffA[s]];
                unsigned al1 = s_lo[base1 + koffA[s]];
                unsigned al2 = s_lo[base0 + koffB[s]];
                unsigned al3 = s_lo[base1 + koffB[s]];
                #pragma unroll
                for (int nt = 0; nt < 2; ++nt) {
                    MMA_TF32(c[nt][0], c[nt][1], c[nt][2], c[nt][3],
                             ah0, ah1, ah2, ah3,
                             bhi[nt][s][0], bhi[nt][s][1]);
                    MMA_TF32(c[nt][0], c[nt][1], c[nt][2], c[nt][3],
                             ah0, ah1, ah2, ah3,
                             blo[nt][s][0], blo[nt][s][1]);
                    MMA_TF32(c[nt][0], c[nt][1], c[nt][2], c[nt][3],
                             al0, al1, al2, al3,
                             bhi[nt][s][0], bhi[nt][s][1]);
                }
            }

            if (p == 0) {
                #pragma unroll
                for (int nt = 0; nt < 2; ++nt)
                    #pragma unroll
                    for (int e = 0; e < 4; ++e) pc[nt][e] = c[nt][e];
            } else {
                #pragma unroll
                for (int nt = 0; nt < 2; ++nt)
                    #pragma unroll
                    for (int e = 0; e < 4; ++e)
                        pc[nt][e] = fmaxf(pc[nt][e], c[nt][e]);
            }
        }

        // bias + relu in registers
        #pragma unroll
        for (int nt = 0; nt < 2; ++nt) {
            pc[nt][0] = fmaxf(pc[nt][0] + cbias[nt][0], 0.f);
            pc[nt][1] = fmaxf(pc[nt][1] + cbias[nt][1], 0.f);
            pc[nt][2] = fmaxf(pc[nt][2] + cbias[nt][0], 0.f);
            pc[nt][3] = fmaxf(pc[nt][3] + cbias[nt][1], 0.f);
        }

        // pack pooled frags -> fp16 A (16 img x 16 ch)
        unsigned a0 = pack_h2(pc[0][0], pc[0][1]);
        unsigned a1 = pack_h2(pc[0][2], pc[0][3]);
        unsigned a2 = pack_h2(pc[1][0], pc[1][1]);
        unsigned a3 = pack_h2(pc[1][2], pc[1][3]);

        MMA_F16(dc[0][0], dc[0][1], dc[0][2], dc[0][3],
                a0, a1, a2, a3, Bv.x, Bv.y);
        MMA_F16(dc[1][0], dc[1][1], dc[1][2], dc[1][3],
                a0, a1, a2, a3, Bv.z, Bv.w);
    }

    // ---- reduce 12 warps' partial dense C, bias, log_softmax ----
    __syncthreads();                        // everyone done reading image planes
    float* s_red = (float*)s_mem;           // [12][16 img][16 out]
    float* s_log = (float*)s_mem + 12 * 256;
    {
        float* wr = s_red + warp * 256;
        wr[ g      * 16 + 2 * tid    ] = dc[0][0];
        wr[ g      * 16 + 2 * tid + 1] = dc[0][1];
        wr[(g + 8) * 16 + 2 * tid    ] = dc[0][2];
        wr[(g + 8) * 16 + 2 * tid + 1] = dc[0][3];
        wr[ g      * 16 + 8 + 2 * tid    ] = dc[1][0];
        wr[ g      * 16 + 8 + 2 * tid + 1] = dc[1][1];
        wr[(g + 8) * 16 + 8 + 2 * tid    ] = dc[1][2];
        wr[(g + 8) * 16 + 8 + 2 * tid + 1] = dc[1][3];
    }
    __syncthreads();

    if (t < 160) {
        int img = t / 10, o = t % 10;
        float s = 0.f;
        #pragma unroll
        for (int wp = 0; wp < 12; ++wp) s += s_red[wp * 256 + img * 16 + o];
        s_log[t] = s + P[OFF_BDENSE + o];
    }
    __syncthreads();

    if (t < 16) {
        float v[10], m = -1e30f;
        #pragma unroll
        for (int o = 0; o < 10; ++o) { v[o] = s_log[t * 10 + o]; m = fmaxf(m, v[o]); }
        float su = 0.f;
        #pragma unroll
        for (int o = 0; o < 10; ++o) su += expf(v[o] - m);
        float ls = m + logf(su);
        float* op = out + ((size_t)init * 128 + n0 + t) * 10;
        #pragma unroll
        for (int o = 0; o < 10; ++o) op[o] = v[o] - ls;
    }
}

// ============================================================================
extern "C" void kernel_launch(void* const* d_in, const int* in_sizes, int n_in,
                              void* d_out, int out_size)
{
    const float* params = (const float*)d_in[0];   // [64, 46922]
    const float* batch  = (const float*)d_in[1];   // [128, 1, 28, 28]
    float* out          = (float*)d_out;           // [64, 128, 10]

    cudaFuncSetAttribute(fused_kernel,
                         cudaFuncAttributeMaxDynamicSharedMemorySize, K1_SMEM);

    prep_wd_kernel<<<128, 256>>>(params);
    fused_kernel<<<512, K1_THREADS, K1_SMEM>>>(params, batch, out);
}